// round 12
// baseline (speedup 1.0000x reference)
#include <cuda_runtime.h>
#include <cuda_fp16.h>
#include <math.h>
#include <stdint.h>

// Problem constants
#define BB   16
#define CC   192
#define HH   128
#define WW   128
#define HW   16384
#define C3   576
#define HEADS 4
#define HD   48
#define TN   16384
#define KSPLIT 8

// ---------------------------------------------------------------------------
// Scratch
// ---------------------------------------------------------------------------
__device__ __half g_xh  [(size_t)BB * CC * HW];   // x in fp16
__device__ __half g_wh  [C3 * CC];                // wqkv in fp16
__device__ __half g_qkv [(size_t)BB * C3 * HW];   // qkv (pre-dwconv), fp16
__device__ __half g_qkvd[(size_t)BB * C3 * HW];   // post-dwconv, fp16
__device__ float  g_S   [BB * HEADS * HD * HD];
__device__ float  g_n2  [BB * HEADS * 2 * HD];
__device__ __half g_M   [BB * CC * CC];           // fused proj matrix, fp16

// ---------------------------------------------------------------------------
// helpers
// ---------------------------------------------------------------------------
__global__ void zero2_kernel(float* a, int na, float* b, int nb) {
    int i = blockIdx.x * blockDim.x + threadIdx.x;
    if (i < na) a[i] = 0.f;
    if (i < nb) b[i] = 0.f;
}

__global__ __launch_bounds__(256)
void f2h_kernel(const float* __restrict__ src, __half* __restrict__ dst, size_t n) {
    size_t i = ((size_t)blockIdx.x * blockDim.x + threadIdx.x) * 8;
    if (i + 8 <= n) {
        float4 a = *(const float4*)(src + i);
        float4 b = *(const float4*)(src + i + 4);
        __half2 h[4] = {__floats2half2_rn(a.x, a.y), __floats2half2_rn(a.z, a.w),
                        __floats2half2_rn(b.x, b.y), __floats2half2_rn(b.z, b.w)};
        *(uint4*)(dst + i) = *(uint4*)h;
    } else {
        for (; i < n; i++) dst[i] = __float2half_rn(src[i]);
    }
}

__device__ __forceinline__ void mma_f16(float* c, const unsigned* a, const unsigned* b) {
    asm volatile(
        "mma.sync.aligned.m16n8k16.row.col.f32.f16.f16.f32 "
        "{%0,%1,%2,%3}, {%4,%5,%6,%7}, {%8,%9}, {%0,%1,%2,%3};"
        : "+f"(c[0]), "+f"(c[1]), "+f"(c[2]), "+f"(c[3])
        : "r"(a[0]), "r"(a[1]), "r"(a[2]), "r"(a[3]), "r"(b[0]), "r"(b[1]));
}
__device__ __forceinline__ void ldsm_x4(unsigned* r, uint32_t addr) {
    asm volatile("ldmatrix.sync.aligned.m8n8.x4.shared.b16 {%0,%1,%2,%3}, [%4];"
                 : "=r"(r[0]), "=r"(r[1]), "=r"(r[2]), "=r"(r[3]) : "r"(addr));
}
__device__ __forceinline__ void ldsm_x2_t(unsigned* r, uint32_t addr) {
    asm volatile("ldmatrix.sync.aligned.m8n8.x2.trans.shared.b16 {%0,%1}, [%2];"
                 : "=r"(r[0]), "=r"(r[1]) : "r"(addr));
}
__device__ __forceinline__ void cpasync16(uint32_t smem, const void* g) {
    asm volatile("cp.async.ca.shared.global [%0], [%1], 16;" :: "r"(smem), "l"(g));
}
__device__ __forceinline__ void cp_commit() { asm volatile("cp.async.commit_group;"); }
template <int N>
__device__ __forceinline__ void cp_wait() { asm volatile("cp.async.wait_group %0;" :: "n"(N)); }

// ---------------------------------------------------------------------------
// fp16 TC GEMM, all-fp16 operands, 4-stage cp.async pipeline (dynamic smem).
// C[M x 16384] = A[M x K] * B[K x 16384]; C type templated (half / float).
// 128x128 tile, BK=32, 8 warps (2x4), warp tile 64x32.
// ---------------------------------------------------------------------------
#define GBM 128
#define GBN 128
#define GBK 32
#define APITCH 40
#define BPITCH 136
#define GSTAGES 4
#define STAGE_A (GBM * APITCH)          // halves per A stage (5120)
#define STAGE_B (GBK * BPITCH)          // halves per B stage (4352)
#define GEMM_SMEM ((GSTAGES * (STAGE_A + STAGE_B)) * 2)   // 75776 B

template <typename CT>
__global__ __launch_bounds__(256)
void gemm_h(const __half* __restrict__ Ag, const __half* __restrict__ Bg,
            CT* __restrict__ Cg, int M, int K,
            size_t sA, size_t sB, size_t sC) {
    extern __shared__ __half sm[];
    __half* As = sm;                          // [GSTAGES][STAGE_A]
    __half* Bs = sm + GSTAGES * STAGE_A;      // [GSTAGES][STAGE_B]

    Ag += (size_t)blockIdx.z * sA;
    Bg += (size_t)blockIdx.z * sB;
    Cg += (size_t)blockIdx.z * sC;
    const int m0 = blockIdx.x * GBM;
    const int n0 = blockIdx.y * GBN;
    const int tid = threadIdx.x;
    const int warp = tid >> 5, lane = tid & 31;
    const int wm = (warp >> 2) * 64;
    const int wn = (warp & 3) * 32;

    float acc[4][4][4];
#pragma unroll
    for (int i = 0; i < 4; i++)
#pragma unroll
        for (int j = 0; j < 4; j++)
#pragma unroll
            for (int l = 0; l < 4; l++) acc[i][j][l] = 0.f;

    const int NK = K / GBK;

    const uint32_t aBase = (uint32_t)__cvta_generic_to_shared(As);
    const uint32_t bBase = (uint32_t)__cvta_generic_to_shared(Bs);

    auto issue = [&](int it) {
        const int st = it & (GSTAGES - 1);
        const int k0 = it * GBK;
#pragma unroll
        for (int i = 0; i < 2; i++) {
            int idx = tid * 2 + i;                 // A: 512 x 16B
            int row = idx >> 2, seg = idx & 3;
            int r = m0 + row; if (r >= M) r = M - 1;
            cpasync16(aBase + (st * STAGE_A + row * APITCH + seg * 8) * 2,
                      Ag + (size_t)r * K + k0 + seg * 8);
        }
#pragma unroll
        for (int i = 0; i < 2; i++) {
            int idx = tid * 2 + i;                 // B: 512 x 16B
            int k = idx >> 4, seg = idx & 15;
            cpasync16(bBase + (st * STAGE_B + k * BPITCH + seg * 8) * 2,
                      Bg + (size_t)(k0 + k) * TN + n0 + seg * 8);
        }
        cp_commit();
    };

    issue(0);
    if (NK > 1) issue(1);
    if (NK > 2) issue(2);

    const int arow = wm + (lane & 15);
    const int acolh = (lane >> 4) << 3;
    const int brow = lane & 15;

    for (int it = 0; it < NK; it++) {
        if (it + 3 < NK) issue(it + 3);
        else cp_commit();                       // empty group keeps count exact
        cp_wait<3>();
        __syncthreads();

        const int st = it & (GSTAGES - 1);
        const uint32_t aB = aBase + st * STAGE_A * 2;
        const uint32_t bB = bBase + st * STAGE_B * 2;
#pragma unroll
        for (int ks = 0; ks < GBK; ks += 16) {
            unsigned af[4][4];
#pragma unroll
            for (int mt = 0; mt < 4; mt++)
                ldsm_x4(af[mt], aB + ((arow + mt * 16) * APITCH + ks + acolh) * 2);
            unsigned bf[4][2];
#pragma unroll
            for (int nt = 0; nt < 4; nt++)
                ldsm_x2_t(bf[nt], bB + ((ks + brow) * BPITCH + wn + nt * 8) * 2);
#pragma unroll
            for (int mt = 0; mt < 4; mt++)
#pragma unroll
                for (int nt = 0; nt < 4; nt++)
                    mma_f16(acc[mt][nt], af[mt], bf[nt]);
        }
        __syncthreads();
    }

    // epilogue
    const int frow = lane >> 2;
    const int qc = (lane & 3) * 2;
#pragma unroll
    for (int mt = 0; mt < 4; mt++) {
        int gr = m0 + wm + mt * 16 + frow;
#pragma unroll
        for (int nt = 0; nt < 4; nt++) {
            int gc = n0 + wn + nt * 8 + qc;
            if (sizeof(CT) == 2) {
                if (gr < M)
                    *(__half2*)((__half*)Cg + (size_t)gr * TN + gc) =
                        __floats2half2_rn(acc[mt][nt][0], acc[mt][nt][1]);
                if (gr + 8 < M)
                    *(__half2*)((__half*)Cg + (size_t)(gr + 8) * TN + gc) =
                        __floats2half2_rn(acc[mt][nt][2], acc[mt][nt][3]);
            } else {
                if (gr < M)
                    *(float2*)((float*)Cg + (size_t)gr * TN + gc) =
                        make_float2(acc[mt][nt][0], acc[mt][nt][1]);
                if (gr + 8 < M)
                    *(float2*)((float*)Cg + (size_t)(gr + 8) * TN + gc) =
                        make_float2(acc[mt][nt][2], acc[mt][nt][3]);
            }
        }
    }
}

// ---------------------------------------------------------------------------
// Depthwise 3x3: fp16 in -> fp16 out + fp32 norms of rounded values
// ---------------------------------------------------------------------------
__global__ __launch_bounds__(256)
void dwconv_h(const __half* __restrict__ in, const float* __restrict__ wdw,
              __half* __restrict__ out, float* __restrict__ norm2) {
    const int y0 = blockIdx.x * 32;
    const int ch = blockIdx.y;
    const int b  = blockIdx.z;
    const __half* base = in + ((size_t)b * C3 + ch) * HW;
    __half* obase = out + ((size_t)b * C3 + ch) * HW;

    __shared__ float t[34][136];

    if (threadIdx.x < 34) {
        t[threadIdx.x][3]   = 0.f;
        t[threadIdx.x][132] = 0.f;
    }
    for (int i = threadIdx.x; i < 34 * 32; i += 256) {
        int r = i >> 5, j = i & 31;
        int gy = y0 - 1 + r;
        float4 v = make_float4(0.f, 0.f, 0.f, 0.f);
        if (gy >= 0 && gy < HH) {
            uint2 u = *(const uint2*)(base + gy * WW + 4 * j);
            __half2 h0 = *(__half2*)&u.x;
            __half2 h1 = *(__half2*)&u.y;
            v = make_float4(__low2float(h0), __high2float(h0),
                            __low2float(h1), __high2float(h1));
        }
        *(float4*)&t[r][4 + 4 * j] = v;
    }
    __syncthreads();

    float w[9];
#pragma unroll
    for (int i = 0; i < 9; i++) w[i] = wdw[ch * 9 + i];

    const int ry = threadIdx.x >> 5;
    const int x0 = (threadIdx.x & 31) << 2;
    const int c  = 4 + x0;

    float ss = 0.f;
#pragma unroll
    for (int jj = 0; jj < 4; jj++) {
        int y = ry * 4 + jj;
        float4 o = make_float4(0.f, 0.f, 0.f, 0.f);
#pragma unroll
        for (int dy = 0; dy < 3; dy++) {
            const float* rr = t[y + dy];
            float4 v = *(const float4*)&rr[c];
            float  l = rr[c - 1];
            float  rg = rr[c + 4];
            float w0 = w[dy * 3 + 0], w1 = w[dy * 3 + 1], w2 = w[dy * 3 + 2];
            o.x += l   * w0 + v.x * w1 + v.y * w2;
            o.y += v.x * w0 + v.y * w1 + v.z * w2;
            o.z += v.y * w0 + v.z * w1 + v.w * w2;
            o.w += v.z * w0 + v.w * w1 + rg  * w2;
        }
        __half2 h01 = __floats2half2_rn(o.x, o.y);
        __half2 h23 = __floats2half2_rn(o.z, o.w);
        *(__half2*)(obase + (y0 + y) * WW + x0)     = h01;
        *(__half2*)(obase + (y0 + y) * WW + x0 + 2) = h23;
        float r0 = __low2float(h01), r1 = __high2float(h01);
        float r2 = __low2float(h23), r3 = __high2float(h23);
        ss += r0 * r0 + r1 * r1 + r2 * r2 + r3 * r3;
    }

    if (ch < 2 * CC) {
#pragma unroll
        for (int off = 16; off > 0; off >>= 1)
            ss += __shfl_down_sync(0xffffffffu, ss, off);
        __shared__ float wsum[8];
        if ((threadIdx.x & 31) == 0) wsum[threadIdx.x >> 5] = ss;
        __syncthreads();
        if (threadIdx.x == 0) {
            float tsum = 0.f;
#pragma unroll
            for (int i = 0; i < 8; i++) tsum += wsum[i];
            int idx;
            if (ch < CC) idx = (b * HEADS + ch / HD) * (2 * HD) + (ch % HD);
            else { int c2 = ch - CC; idx = (b * HEADS + c2 / HD) * (2 * HD) + HD + (c2 % HD); }
            atomicAdd(&norm2[idx], tsum);
        }
    }
}

// ---------------------------------------------------------------------------
// Gram via fp16 MMA, fragments direct from gmem
// ---------------------------------------------------------------------------
__global__ __launch_bounds__(256)
void gram_mma(const __half* __restrict__ qkvd, float* __restrict__ S) {
    const int bh = blockIdx.x;
    const int b = bh / HEADS, h = bh % HEADS;
    const __half* Q  = qkvd + ((size_t)b * C3 + h * HD) * HW;
    const __half* Kp = qkvd + ((size_t)b * C3 + CC + h * HD) * HW;

    __shared__ float Ssh[HD * HD];
    for (int i = threadIdx.x; i < HD * HD; i += 256) Ssh[i] = 0.f;
    __syncthreads();

    const int warp = threadIdx.x >> 5, lane = threadIdx.x & 31;
    const int g  = lane >> 2;
    const int cq = (lane & 3) << 1;

    const int span = HW / (KSPLIT * 8);
    const int pc0 = (blockIdx.y * 8 + warp) * span;

    float acc[3][6][4];
#pragma unroll
    for (int i = 0; i < 3; i++)
#pragma unroll
        for (int j = 0; j < 6; j++)
#pragma unroll
            for (int l = 0; l < 4; l++) acc[i][j][l] = 0.f;

    for (int pc = pc0; pc < pc0 + span; pc += 16) {
        unsigned af[3][4], bf[6][2];
#pragma unroll
        for (int mt = 0; mt < 3; mt++) {
            const __half* qr = Q + (size_t)(mt * 16 + g) * HW + pc + cq;
            af[mt][0] = *(const unsigned*)(qr);
            af[mt][1] = *(const unsigned*)(qr + 8 * HW);
            af[mt][2] = *(const unsigned*)(qr + 8);
            af[mt][3] = *(const unsigned*)(qr + 8 * HW + 8);
        }
#pragma unroll
        for (int nt = 0; nt < 6; nt++) {
            const __half* kr = Kp + (size_t)(nt * 8 + g) * HW + pc + cq;
            bf[nt][0] = *(const unsigned*)(kr);
            bf[nt][1] = *(const unsigned*)(kr + 8);
        }
#pragma unroll
        for (int mt = 0; mt < 3; mt++)
#pragma unroll
            for (int nt = 0; nt < 6; nt++)
                mma_f16(acc[mt][nt], af[mt], bf[nt]);
    }

#pragma unroll
    for (int mt = 0; mt < 3; mt++) {
#pragma unroll
        for (int nt = 0; nt < 6; nt++) {
            int r0 = mt * 16 + g;
            int c0 = nt * 8 + cq;
            atomicAdd(&Ssh[r0 * HD + c0],           acc[mt][nt][0]);
            atomicAdd(&Ssh[r0 * HD + c0 + 1],       acc[mt][nt][1]);
            atomicAdd(&Ssh[(r0 + 8) * HD + c0],     acc[mt][nt][2]);
            atomicAdd(&Ssh[(r0 + 8) * HD + c0 + 1], acc[mt][nt][3]);
        }
    }
    __syncthreads();

    float* Sg = S + (size_t)bh * HD * HD;
    for (int i = threadIdx.x; i < HD * HD; i += 256)
        atomicAdd(&Sg[i], Ssh[i]);
}

// ---------------------------------------------------------------------------
// Softmax (48) + M = Wproj @ blockdiag(attn) -> fp16, one block per batch
// ---------------------------------------------------------------------------
__global__ __launch_bounds__(256)
void softmax_M_kernel(float* __restrict__ S, const float* __restrict__ norm2,
                      const float* __restrict__ temperature,
                      const float* __restrict__ Wp, __half* __restrict__ Mm) {
    const int b = blockIdx.x;
    const int t = threadIdx.x;

    if (t < HEADS * HD) {
        int h = t / HD, i = t % HD;
        int bh = b * HEADS + h;
        const float* n2 = norm2 + bh * (2 * HD);
        float nq = fmaxf(sqrtf(n2[i]), 1e-12f);
        float tv = temperature[h];
        float* Srow = S + ((size_t)bh * HD + i) * HD;

        float row[48];
        float mx = -1e30f;
#pragma unroll
        for (int j = 0; j < HD; j++) {
            float nk = fmaxf(sqrtf(n2[HD + j]), 1e-12f);
            row[j] = Srow[j] / (nq * nk) * tv;
            mx = fmaxf(mx, row[j]);
        }
        float sum = 0.f;
#pragma unroll
        for (int j = 0; j < HD; j++) {
            row[j] = expf(row[j] - mx);
            sum += row[j];
        }
        float inv = 1.f / sum;
#pragma unroll
        for (int j = 0; j < HD; j++) Srow[j] = row[j] * inv;
    }
    __syncthreads();

    const float* attn = S;
    for (int idx = t; idx < CC * CC; idx += blockDim.x) {
        int o = idx / CC, d = idx % CC;
        int h = d / HD, dl = d % HD;
        const float* wrow = Wp + o * CC + h * HD;
        const float* acol = attn + ((size_t)(b * HEADS + h) * HD) * HD + dl;
        float s = 0.f;
#pragma unroll
        for (int cl = 0; cl < HD; cl++)
            s += wrow[cl] * acol[(size_t)cl * HD];
        Mm[(size_t)b * CC * CC + idx] = __float2half_rn(s);
    }
}

// ---------------------------------------------------------------------------
// Launch
// ---------------------------------------------------------------------------
extern "C" void kernel_launch(void* const* d_in, const int* in_sizes, int n_in,
                              void* d_out, int out_size) {
    const float* x     = (const float*)d_in[0];
    const float* wqkv  = (const float*)d_in[1];
    const float* wdw   = (const float*)d_in[2];
    const float* wproj = (const float*)d_in[3];
    const float* temp  = (const float*)d_in[4];
    float* out = (float*)d_out;

    __half *xh_p, *wh_p, *qkv_p, *qkvd_p, *M_p;
    float *S_p, *n2_p;
    cudaGetSymbolAddress((void**)&xh_p,   g_xh);
    cudaGetSymbolAddress((void**)&wh_p,   g_wh);
    cudaGetSymbolAddress((void**)&qkv_p,  g_qkv);
    cudaGetSymbolAddress((void**)&qkvd_p, g_qkvd);
    cudaGetSymbolAddress((void**)&S_p,    g_S);
    cudaGetSymbolAddress((void**)&n2_p,   g_n2);
    cudaGetSymbolAddress((void**)&M_p,    g_M);

    cudaFuncSetAttribute(gemm_h<__half>, cudaFuncAttributeMaxDynamicSharedMemorySize, GEMM_SMEM);
    cudaFuncSetAttribute(gemm_h<float>,  cudaFuncAttributeMaxDynamicSharedMemorySize, GEMM_SMEM);

    // 1. zero accumulators + fp16 conversions
    {
        int nS = BB * HEADS * HD * HD;
        int nN = BB * HEADS * 2 * HD;
        zero2_kernel<<<(nS + 255) / 256, 256>>>(S_p, nS, n2_p, nN);
        size_t nx = (size_t)BB * CC * HW;
        f2h_kernel<<<(unsigned)((nx / 8 + 255) / 256), 256>>>(x, xh_p, nx);
        size_t nw = (size_t)C3 * CC;
        f2h_kernel<<<(unsigned)((nw / 8 + 255) / 256), 256>>>(wqkv, wh_p, nw);
    }

    // 2. qkv = Wqkv @ x
    {
        dim3 grid((C3 + GBM - 1) / GBM, TN / GBN, BB);
        gemm_h<__half><<<grid, 256, GEMM_SMEM>>>(wh_p, xh_p, qkv_p, C3, CC,
                                                 0, (size_t)CC * HW, (size_t)C3 * HW);
    }

    // 3. depthwise 3x3 + norms
    {
        dim3 grid(HH / 32, C3, BB);
        dwconv_h<<<grid, 256>>>(qkv_p, wdw, qkvd_p, n2_p);
    }

    // 4. Gram via MMA
    {
        dim3 grid(BB * HEADS, KSPLIT);
        gram_mma<<<grid, 256>>>(qkvd_p, S_p);
    }

    // 5. softmax + M build
    softmax_M_kernel<<<BB, 256>>>(S_p, n2_p, temp, wproj, M_p);

    // 6. out = M @ v
    {
        dim3 grid((CC + GBM - 1) / GBM, TN / GBN, BB);
        gemm_h<float><<<grid, 256, GEMM_SMEM>>>(M_p, qkvd_p + (size_t)2 * CC * HW, out, CC, CC,
                                                (size_t)CC * CC, (size_t)C3 * HW, (size_t)CC * HW);
    }
}

// round 13
// speedup vs baseline: 1.0041x; 1.0041x over previous
#include <cuda_runtime.h>
#include <cuda_fp16.h>
#include <math.h>
#include <stdint.h>

// Problem constants
#define BB   16
#define CC   192
#define HH   128
#define WW   128
#define HW   16384
#define C3   576
#define HEADS 4
#define HD   48
#define TN   16384
#define KSPLIT 8

// ---------------------------------------------------------------------------
// Scratch
// ---------------------------------------------------------------------------
__device__ __half g_xh  [(size_t)BB * CC * HW];   // x in fp16
__device__ __half g_wh  [C3 * CC];                // wqkv in fp16
__device__ __half g_qkv [(size_t)BB * C3 * HW];   // qkv (pre-dwconv), fp16
__device__ __half g_qkvd[(size_t)BB * C3 * HW];   // post-dwconv, fp16
__device__ float  g_S   [BB * HEADS * HD * HD];
__device__ float  g_n2  [BB * HEADS * 2 * HD];
__device__ __half g_M   [BB * CC * CC];           // fused proj matrix, fp16

// ---------------------------------------------------------------------------
// helpers
// ---------------------------------------------------------------------------
__global__ void zero2_kernel(float* a, int na, float* b, int nb) {
    int i = blockIdx.x * blockDim.x + threadIdx.x;
    if (i < na) a[i] = 0.f;
    if (i < nb) b[i] = 0.f;
}

__global__ __launch_bounds__(256)
void f2h_kernel(const float* __restrict__ src, __half* __restrict__ dst, size_t n) {
    size_t i = ((size_t)blockIdx.x * blockDim.x + threadIdx.x) * 8;
    if (i + 8 <= n) {
        float4 a = *(const float4*)(src + i);
        float4 b = *(const float4*)(src + i + 4);
        __half2 h[4] = {__floats2half2_rn(a.x, a.y), __floats2half2_rn(a.z, a.w),
                        __floats2half2_rn(b.x, b.y), __floats2half2_rn(b.z, b.w)};
        *(uint4*)(dst + i) = *(uint4*)h;
    } else {
        for (; i < n; i++) dst[i] = __float2half_rn(src[i]);
    }
}

__device__ __forceinline__ void mma_f16(float* c, const unsigned* a, const unsigned* b) {
    asm volatile(
        "mma.sync.aligned.m16n8k16.row.col.f32.f16.f16.f32 "
        "{%0,%1,%2,%3}, {%4,%5,%6,%7}, {%8,%9}, {%0,%1,%2,%3};"
        : "+f"(c[0]), "+f"(c[1]), "+f"(c[2]), "+f"(c[3])
        : "r"(a[0]), "r"(a[1]), "r"(a[2]), "r"(a[3]), "r"(b[0]), "r"(b[1]));
}
__device__ __forceinline__ void ldsm_x4(unsigned* r, uint32_t addr) {
    asm volatile("ldmatrix.sync.aligned.m8n8.x4.shared.b16 {%0,%1,%2,%3}, [%4];"
                 : "=r"(r[0]), "=r"(r[1]), "=r"(r[2]), "=r"(r[3]) : "r"(addr));
}
__device__ __forceinline__ void ldsm_x2_t(unsigned* r, uint32_t addr) {
    asm volatile("ldmatrix.sync.aligned.m8n8.x2.trans.shared.b16 {%0,%1}, [%2];"
                 : "=r"(r[0]), "=r"(r[1]) : "r"(addr));
}
__device__ __forceinline__ void cpasync16(uint32_t smem, const void* g) {
    asm volatile("cp.async.ca.shared.global [%0], [%1], 16;" :: "r"(smem), "l"(g));
}
__device__ __forceinline__ void cp_commit() { asm volatile("cp.async.commit_group;"); }
template <int N>
__device__ __forceinline__ void cp_wait() { asm volatile("cp.async.wait_group %0;" :: "n"(N)); }

// ---------------------------------------------------------------------------
// fp16 TC GEMM, all-fp16 operands, 4-stage cp.async pipeline (dynamic smem).
// C[M x 16384] = A[M x K] * B[K x 16384]; C type templated (half / float).
// 128x128 tile, BK=32, 8 warps (2x4), warp tile 64x32.
// ---------------------------------------------------------------------------
#define GBM 128
#define GBN 128
#define GBK 32
#define APITCH 40
#define BPITCH 136
#define GSTAGES 4
#define STAGE_A (GBM * APITCH)          // halves per A stage (5120)
#define STAGE_B (GBK * BPITCH)          // halves per B stage (4352)
#define GEMM_SMEM ((GSTAGES * (STAGE_A + STAGE_B)) * 2)   // 75776 B

template <typename CT>
__global__ __launch_bounds__(256)
void gemm_h(const __half* __restrict__ Ag, const __half* __restrict__ Bg,
            CT* __restrict__ Cg, int M, int K,
            size_t sA, size_t sB, size_t sC) {
    extern __shared__ __half sm[];
    __half* As = sm;                          // [GSTAGES][STAGE_A]
    __half* Bs = sm + GSTAGES * STAGE_A;      // [GSTAGES][STAGE_B]

    Ag += (size_t)blockIdx.z * sA;
    Bg += (size_t)blockIdx.z * sB;
    Cg += (size_t)blockIdx.z * sC;
    const int m0 = blockIdx.x * GBM;
    const int n0 = blockIdx.y * GBN;
    const int tid = threadIdx.x;
    const int warp = tid >> 5, lane = tid & 31;
    const int wm = (warp >> 2) * 64;
    const int wn = (warp & 3) * 32;

    float acc[4][4][4];
#pragma unroll
    for (int i = 0; i < 4; i++)
#pragma unroll
        for (int j = 0; j < 4; j++)
#pragma unroll
            for (int l = 0; l < 4; l++) acc[i][j][l] = 0.f;

    const int NK = K / GBK;

    const uint32_t aBase = (uint32_t)__cvta_generic_to_shared(As);
    const uint32_t bBase = (uint32_t)__cvta_generic_to_shared(Bs);

    auto issue = [&](int it) {
        const int st = it & (GSTAGES - 1);
        const int k0 = it * GBK;
#pragma unroll
        for (int i = 0; i < 2; i++) {
            int idx = tid * 2 + i;                 // A: 512 x 16B
            int row = idx >> 2, seg = idx & 3;
            int r = m0 + row; if (r >= M) r = M - 1;
            cpasync16(aBase + (st * STAGE_A + row * APITCH + seg * 8) * 2,
                      Ag + (size_t)r * K + k0 + seg * 8);
        }
#pragma unroll
        for (int i = 0; i < 2; i++) {
            int idx = tid * 2 + i;                 // B: 512 x 16B
            int k = idx >> 4, seg = idx & 15;
            cpasync16(bBase + (st * STAGE_B + k * BPITCH + seg * 8) * 2,
                      Bg + (size_t)(k0 + k) * TN + n0 + seg * 8);
        }
        cp_commit();
    };

    issue(0);
    if (NK > 1) issue(1);
    if (NK > 2) issue(2);

    const int arow = wm + (lane & 15);
    const int acolh = (lane >> 4) << 3;
    const int brow = lane & 15;

    for (int it = 0; it < NK; it++) {
        if (it + 3 < NK) issue(it + 3);
        else cp_commit();                       // empty group keeps count exact
        cp_wait<3>();
        __syncthreads();

        const int st = it & (GSTAGES - 1);
        const uint32_t aB = aBase + st * STAGE_A * 2;
        const uint32_t bB = bBase + st * STAGE_B * 2;
#pragma unroll
        for (int ks = 0; ks < GBK; ks += 16) {
            unsigned af[4][4];
#pragma unroll
            for (int mt = 0; mt < 4; mt++)
                ldsm_x4(af[mt], aB + ((arow + mt * 16) * APITCH + ks + acolh) * 2);
            unsigned bf[4][2];
#pragma unroll
            for (int nt = 0; nt < 4; nt++)
                ldsm_x2_t(bf[nt], bB + ((ks + brow) * BPITCH + wn + nt * 8) * 2);
#pragma unroll
            for (int mt = 0; mt < 4; mt++)
#pragma unroll
                for (int nt = 0; nt < 4; nt++)
                    mma_f16(acc[mt][nt], af[mt], bf[nt]);
        }
        __syncthreads();
    }

    // epilogue
    const int frow = lane >> 2;
    const int qc = (lane & 3) * 2;
#pragma unroll
    for (int mt = 0; mt < 4; mt++) {
        int gr = m0 + wm + mt * 16 + frow;
#pragma unroll
        for (int nt = 0; nt < 4; nt++) {
            int gc = n0 + wn + nt * 8 + qc;
            if (sizeof(CT) == 2) {
                if (gr < M)
                    *(__half2*)((__half*)Cg + (size_t)gr * TN + gc) =
                        __floats2half2_rn(acc[mt][nt][0], acc[mt][nt][1]);
                if (gr + 8 < M)
                    *(__half2*)((__half*)Cg + (size_t)(gr + 8) * TN + gc) =
                        __floats2half2_rn(acc[mt][nt][2], acc[mt][nt][3]);
            } else {
                if (gr < M)
                    *(float2*)((float*)Cg + (size_t)gr * TN + gc) =
                        make_float2(acc[mt][nt][0], acc[mt][nt][1]);
                if (gr + 8 < M)
                    *(float2*)((float*)Cg + (size_t)(gr + 8) * TN + gc) =
                        make_float2(acc[mt][nt][2], acc[mt][nt][3]);
            }
        }
    }
}

// ---------------------------------------------------------------------------
// Depthwise 3x3: fp16 in -> fp16 out + fp32 norms of rounded values
// ---------------------------------------------------------------------------
__global__ __launch_bounds__(256)
void dwconv_h(const __half* __restrict__ in, const float* __restrict__ wdw,
              __half* __restrict__ out, float* __restrict__ norm2) {
    const int y0 = blockIdx.x * 32;
    const int ch = blockIdx.y;
    const int b  = blockIdx.z;
    const __half* base = in + ((size_t)b * C3 + ch) * HW;
    __half* obase = out + ((size_t)b * C3 + ch) * HW;

    __shared__ float t[34][136];

    if (threadIdx.x < 34) {
        t[threadIdx.x][3]   = 0.f;
        t[threadIdx.x][132] = 0.f;
    }
    for (int i = threadIdx.x; i < 34 * 32; i += 256) {
        int r = i >> 5, j = i & 31;
        int gy = y0 - 1 + r;
        float4 v = make_float4(0.f, 0.f, 0.f, 0.f);
        if (gy >= 0 && gy < HH) {
            uint2 u = *(const uint2*)(base + gy * WW + 4 * j);
            __half2 h0 = *(__half2*)&u.x;
            __half2 h1 = *(__half2*)&u.y;
            v = make_float4(__low2float(h0), __high2float(h0),
                            __low2float(h1), __high2float(h1));
        }
        *(float4*)&t[r][4 + 4 * j] = v;
    }
    __syncthreads();

    float w[9];
#pragma unroll
    for (int i = 0; i < 9; i++) w[i] = wdw[ch * 9 + i];

    const int ry = threadIdx.x >> 5;
    const int x0 = (threadIdx.x & 31) << 2;
    const int c  = 4 + x0;

    float ss = 0.f;
#pragma unroll
    for (int jj = 0; jj < 4; jj++) {
        int y = ry * 4 + jj;
        float4 o = make_float4(0.f, 0.f, 0.f, 0.f);
#pragma unroll
        for (int dy = 0; dy < 3; dy++) {
            const float* rr = t[y + dy];
            float4 v = *(const float4*)&rr[c];
            float  l = rr[c - 1];
            float  rg = rr[c + 4];
            float w0 = w[dy * 3 + 0], w1 = w[dy * 3 + 1], w2 = w[dy * 3 + 2];
            o.x += l   * w0 + v.x * w1 + v.y * w2;
            o.y += v.x * w0 + v.y * w1 + v.z * w2;
            o.z += v.y * w0 + v.z * w1 + v.w * w2;
            o.w += v.z * w0 + v.w * w1 + rg  * w2;
        }
        __half2 h01 = __floats2half2_rn(o.x, o.y);
        __half2 h23 = __floats2half2_rn(o.z, o.w);
        *(__half2*)(obase + (y0 + y) * WW + x0)     = h01;
        *(__half2*)(obase + (y0 + y) * WW + x0 + 2) = h23;
        float r0 = __low2float(h01), r1 = __high2float(h01);
        float r2 = __low2float(h23), r3 = __high2float(h23);
        ss += r0 * r0 + r1 * r1 + r2 * r2 + r3 * r3;
    }

    if (ch < 2 * CC) {
#pragma unroll
        for (int off = 16; off > 0; off >>= 1)
            ss += __shfl_down_sync(0xffffffffu, ss, off);
        __shared__ float wsum[8];
        if ((threadIdx.x & 31) == 0) wsum[threadIdx.x >> 5] = ss;
        __syncthreads();
        if (threadIdx.x == 0) {
            float tsum = 0.f;
#pragma unroll
            for (int i = 0; i < 8; i++) tsum += wsum[i];
            int idx;
            if (ch < CC) idx = (b * HEADS + ch / HD) * (2 * HD) + (ch % HD);
            else { int c2 = ch - CC; idx = (b * HEADS + c2 / HD) * (2 * HD) + HD + (c2 % HD); }
            atomicAdd(&norm2[idx], tsum);
        }
    }
}

// ---------------------------------------------------------------------------
// Gram via fp16 MMA, fragments direct from gmem
// ---------------------------------------------------------------------------
__global__ __launch_bounds__(256)
void gram_mma(const __half* __restrict__ qkvd, float* __restrict__ S) {
    const int bh = blockIdx.x;
    const int b = bh / HEADS, h = bh % HEADS;
    const __half* Q  = qkvd + ((size_t)b * C3 + h * HD) * HW;
    const __half* Kp = qkvd + ((size_t)b * C3 + CC + h * HD) * HW;

    __shared__ float Ssh[HD * HD];
    for (int i = threadIdx.x; i < HD * HD; i += 256) Ssh[i] = 0.f;
    __syncthreads();

    const int warp = threadIdx.x >> 5, lane = threadIdx.x & 31;
    const int g  = lane >> 2;
    const int cq = (lane & 3) << 1;

    const int span = HW / (KSPLIT * 8);
    const int pc0 = (blockIdx.y * 8 + warp) * span;

    float acc[3][6][4];
#pragma unroll
    for (int i = 0; i < 3; i++)
#pragma unroll
        for (int j = 0; j < 6; j++)
#pragma unroll
            for (int l = 0; l < 4; l++) acc[i][j][l] = 0.f;

    for (int pc = pc0; pc < pc0 + span; pc += 16) {
        unsigned af[3][4], bf[6][2];
#pragma unroll
        for (int mt = 0; mt < 3; mt++) {
            const __half* qr = Q + (size_t)(mt * 16 + g) * HW + pc + cq;
            af[mt][0] = *(const unsigned*)(qr);
            af[mt][1] = *(const unsigned*)(qr + 8 * HW);
            af[mt][2] = *(const unsigned*)(qr + 8);
            af[mt][3] = *(const unsigned*)(qr + 8 * HW + 8);
        }
#pragma unroll
        for (int nt = 0; nt < 6; nt++) {
            const __half* kr = Kp + (size_t)(nt * 8 + g) * HW + pc + cq;
            bf[nt][0] = *(const unsigned*)(kr);
            bf[nt][1] = *(const unsigned*)(kr + 8);
        }
#pragma unroll
        for (int mt = 0; mt < 3; mt++)
#pragma unroll
            for (int nt = 0; nt < 6; nt++)
                mma_f16(acc[mt][nt], af[mt], bf[nt]);
    }

#pragma unroll
    for (int mt = 0; mt < 3; mt++) {
#pragma unroll
        for (int nt = 0; nt < 6; nt++) {
            int r0 = mt * 16 + g;
            int c0 = nt * 8 + cq;
            atomicAdd(&Ssh[r0 * HD + c0],           acc[mt][nt][0]);
            atomicAdd(&Ssh[r0 * HD + c0 + 1],       acc[mt][nt][1]);
            atomicAdd(&Ssh[(r0 + 8) * HD + c0],     acc[mt][nt][2]);
            atomicAdd(&Ssh[(r0 + 8) * HD + c0 + 1], acc[mt][nt][3]);
        }
    }
    __syncthreads();

    float* Sg = S + (size_t)bh * HD * HD;
    for (int i = threadIdx.x; i < HD * HD; i += 256)
        atomicAdd(&Sg[i], Ssh[i]);
}

// ---------------------------------------------------------------------------
// Softmax (48) + M = Wproj @ blockdiag(attn) -> fp16, one block per batch
// ---------------------------------------------------------------------------
__global__ __launch_bounds__(256)
void softmax_M_kernel(float* __restrict__ S, const float* __restrict__ norm2,
                      const float* __restrict__ temperature,
                      const float* __restrict__ Wp, __half* __restrict__ Mm) {
    const int b = blockIdx.x;
    const int t = threadIdx.x;

    if (t < HEADS * HD) {
        int h = t / HD, i = t % HD;
        int bh = b * HEADS + h;
        const float* n2 = norm2 + bh * (2 * HD);
        float nq = fmaxf(sqrtf(n2[i]), 1e-12f);
        float tv = temperature[h];
        float* Srow = S + ((size_t)bh * HD + i) * HD;

        float row[48];
        float mx = -1e30f;
#pragma unroll
        for (int j = 0; j < HD; j++) {
            float nk = fmaxf(sqrtf(n2[HD + j]), 1e-12f);
            row[j] = Srow[j] / (nq * nk) * tv;
            mx = fmaxf(mx, row[j]);
        }
        float sum = 0.f;
#pragma unroll
        for (int j = 0; j < HD; j++) {
            row[j] = expf(row[j] - mx);
            sum += row[j];
        }
        float inv = 1.f / sum;
#pragma unroll
        for (int j = 0; j < HD; j++) Srow[j] = row[j] * inv;
    }
    __syncthreads();

    const float* attn = S;
    for (int idx = t; idx < CC * CC; idx += blockDim.x) {
        int o = idx / CC, d = idx % CC;
        int h = d / HD, dl = d % HD;
        const float* wrow = Wp + o * CC + h * HD;
        const float* acol = attn + ((size_t)(b * HEADS + h) * HD) * HD + dl;
        float s = 0.f;
#pragma unroll
        for (int cl = 0; cl < HD; cl++)
            s += wrow[cl] * acol[(size_t)cl * HD];
        Mm[(size_t)b * CC * CC + idx] = __float2half_rn(s);
    }
}

// ---------------------------------------------------------------------------
// Launch
// ---------------------------------------------------------------------------
extern "C" void kernel_launch(void* const* d_in, const int* in_sizes, int n_in,
                              void* d_out, int out_size) {
    const float* x     = (const float*)d_in[0];
    const float* wqkv  = (const float*)d_in[1];
    const float* wdw   = (const float*)d_in[2];
    const float* wproj = (const float*)d_in[3];
    const float* temp  = (const float*)d_in[4];
    float* out = (float*)d_out;

    __half *xh_p, *wh_p, *qkv_p, *qkvd_p, *M_p;
    float *S_p, *n2_p;
    cudaGetSymbolAddress((void**)&xh_p,   g_xh);
    cudaGetSymbolAddress((void**)&wh_p,   g_wh);
    cudaGetSymbolAddress((void**)&qkv_p,  g_qkv);
    cudaGetSymbolAddress((void**)&qkvd_p, g_qkvd);
    cudaGetSymbolAddress((void**)&S_p,    g_S);
    cudaGetSymbolAddress((void**)&n2_p,   g_n2);
    cudaGetSymbolAddress((void**)&M_p,    g_M);

    cudaFuncSetAttribute(gemm_h<__half>, cudaFuncAttributeMaxDynamicSharedMemorySize, GEMM_SMEM);
    cudaFuncSetAttribute(gemm_h<float>,  cudaFuncAttributeMaxDynamicSharedMemorySize, GEMM_SMEM);

    // 1. zero accumulators + fp16 conversions
    {
        int nS = BB * HEADS * HD * HD;
        int nN = BB * HEADS * 2 * HD;
        zero2_kernel<<<(nS + 255) / 256, 256>>>(S_p, nS, n2_p, nN);
        size_t nx = (size_t)BB * CC * HW;
        f2h_kernel<<<(unsigned)((nx / 8 + 255) / 256), 256>>>(x, xh_p, nx);
        size_t nw = (size_t)C3 * CC;
        f2h_kernel<<<(unsigned)((nw / 8 + 255) / 256), 256>>>(wqkv, wh_p, nw);
    }

    // 2. qkv = Wqkv @ x
    {
        dim3 grid((C3 + GBM - 1) / GBM, TN / GBN, BB);
        gemm_h<__half><<<grid, 256, GEMM_SMEM>>>(wh_p, xh_p, qkv_p, C3, CC,
                                                 0, (size_t)CC * HW, (size_t)C3 * HW);
    }

    // 3. depthwise 3x3 + norms
    {
        dim3 grid(HH / 32, C3, BB);
        dwconv_h<<<grid, 256>>>(qkv_p, wdw, qkvd_p, n2_p);
    }

    // 4. Gram via MMA
    {
        dim3 grid(BB * HEADS, KSPLIT);
        gram_mma<<<grid, 256>>>(qkvd_p, S_p);
    }

    // 5. softmax + M build
    softmax_M_kernel<<<BB, 256>>>(S_p, n2_p, temp, wproj, M_p);

    // 6. out = M @ v
    {
        dim3 grid((CC + GBM - 1) / GBM, TN / GBN, BB);
        gemm_h<float><<<grid, 256, GEMM_SMEM>>>(M_p, qkvd_p + (size_t)2 * CC * HW, out, CC, CC,
                                                (size_t)CC * CC, (size_t)C3 * HW, (size_t)CC * HW);
    }
}